// round 8
// baseline (speedup 1.0000x reference)
#include <cuda_runtime.h>
#include <math.h>

#define BATCH 32
#define SEQT  512
#define HID   512
#define G4    2048   // 4*HID

// out layout (fp32): out[B][T][2H] @0, h_n[2][B][H] @16777216, c_n @16809984
#define OUT_HN 16777216
#define OUT_CN 16809984

// ---------------------------------------------------------------------------
// Device globals (allocation-free scratch), 256B-aligned for vector access.
// ---------------------------------------------------------------------------
// gx permuted per consumer block: [dir][blk(64)][t(512)][cl(32)][b(32)]
__device__ __align__(256) float g_gx[2][64][SEQT][32][32];
__device__ __align__(256) float g_hT[2][2][HID][BATCH];   // [parity][dir][unit][batch]
// one flag per 128B line: no RMW, each line has 1 writer + 64 readers
__device__ __align__(256) int   g_flags[2][64][32];

// ---------------------------------------------------------------------------
// Packed fp32x2 FMA (Blackwell FFMA2; only reachable via PTX)
// ---------------------------------------------------------------------------
__device__ __forceinline__ float2 f2fma(float2 a, float2 b, float2 c) {
    unsigned long long ra = *reinterpret_cast<unsigned long long*>(&a);
    unsigned long long rb = *reinterpret_cast<unsigned long long*>(&b);
    unsigned long long rc = *reinterpret_cast<unsigned long long*>(&c);
    unsigned long long rd;
    asm("fma.rn.f32x2 %0, %1, %2, %3;" : "=l"(rd) : "l"(ra), "l"(rb), "l"(rc));
    return *reinterpret_cast<float2*>(&rd);
}
__device__ __forceinline__ float2 f2(float x, float y) { return make_float2(x, y); }

__device__ __forceinline__ float sigf(float x) { return 1.0f / (1.0f + __expf(-x)); }
__device__ __forceinline__ float tanhx(float x) { return 2.0f / (1.0f + __expf(-2.0f * x)) - 1.0f; }

// ---------------------------------------------------------------------------
// Phase 1: gx = x @ W_ih^T + biases (written permuted). Init of h/flags is
// embedded (first 128 blocks also copy h0; block 0 resets flags).
// BM=BN=64, BK=16, 256 thr, 4x4 microtile, dup'd-A f32x2 (R2-proven).
// ---------------------------------------------------------------------------
#define BM 64
#define BN 64
#define BK 16

__global__ __launch_bounds__(256) void gemm_ih_kernel(
        const float* __restrict__ x,
        const float* __restrict__ h0,
        const float* __restrict__ w_f, const float* __restrict__ w_r,
        const float* __restrict__ bi_f, const float* __restrict__ bh_f,
        const float* __restrict__ bi_r, const float* __restrict__ bh_r) {
    const int tid = threadIdx.x;

    // ---- embedded init (h0 -> g_hT[0], flags) ----
    {
        const int gid = (blockIdx.z * gridDim.y + blockIdx.y) * gridDim.x + blockIdx.x;
        if (gid < 128) {
            const int idx = gid * 256 + tid;     // 0..32767
            const int dirI = idx >> 14;
            const int bI = (idx >> 9) & 31;
            const int jI = idx & 511;
            g_hT[0][dirI][jI][bI] = h0[idx];
        }
        if (gid == 0 && tid < 128) g_flags[tid >> 6][tid & 63][0] = 0;
    }

    const int dir = blockIdx.z;
    const float* __restrict__ w  = dir ? w_r  : w_f;
    const float* __restrict__ bi = dir ? bi_r : bi_f;
    const float* __restrict__ bh = dir ? bh_r : bh_f;

    const int rm0 = blockIdx.y * BM;   // rows over T*B (row = t*32+b)
    const int cn0 = blockIdx.x * BN;   // cols over 4H

    __shared__ __align__(16) float2 Asd[BK][BM + 2];   // A rows, duplicated lanes
    __shared__ __align__(16) float  Ws[BK][BN + 4];

    const int tr = tid / 16;           // 0..15 row group
    const int tc = tid % 16;           // 0..15 col group

    const int l_row = tid >> 2;        // 0..63
    const int l_k4  = (tid & 3) << 2;  // 0,4,8,12

    const int r  = rm0 + l_row;
    int       tt = r >> 5;
    const int bb = r & 31;
    if (dir) tt = (SEQT - 1) - tt;
    const float* a_ptr = x + ((size_t)bb * SEQT + tt) * HID;
    const float* w_ptr = w + (size_t)(cn0 + l_row) * HID;

    float2 acc[4][2];
#pragma unroll
    for (int i = 0; i < 4; i++) { acc[i][0] = f2(0.f, 0.f); acc[i][1] = f2(0.f, 0.f); }

    for (int k0 = 0; k0 < HID; k0 += BK) {
        float4 av = *(const float4*)(a_ptr + k0 + l_k4);
        float4 wv = *(const float4*)(w_ptr + k0 + l_k4);
        __syncthreads();
        Asd[l_k4 + 0][l_row] = f2(av.x, av.x);
        Asd[l_k4 + 1][l_row] = f2(av.y, av.y);
        Asd[l_k4 + 2][l_row] = f2(av.z, av.z);
        Asd[l_k4 + 3][l_row] = f2(av.w, av.w);
        Ws[l_k4 + 0][l_row] = wv.x;
        Ws[l_k4 + 1][l_row] = wv.y;
        Ws[l_k4 + 2][l_row] = wv.z;
        Ws[l_k4 + 3][l_row] = wv.w;
        __syncthreads();
#pragma unroll
        for (int kk = 0; kk < BK; kk++) {
            float4 ad0 = *(const float4*)&Asd[kk][tr * 4];
            float4 ad1 = *(const float4*)&Asd[kk][tr * 4 + 2];
            float4 w4  = *(const float4*)&Ws[kk][tc * 4];
            float2 w01 = f2(w4.x, w4.y);
            float2 w23 = f2(w4.z, w4.w);
            float2 a0 = f2(ad0.x, ad0.y);
            float2 a1 = f2(ad0.z, ad0.w);
            float2 a2 = f2(ad1.x, ad1.y);
            float2 a3 = f2(ad1.z, ad1.w);
            acc[0][0] = f2fma(a0, w01, acc[0][0]); acc[0][1] = f2fma(a0, w23, acc[0][1]);
            acc[1][0] = f2fma(a1, w01, acc[1][0]); acc[1][1] = f2fma(a1, w23, acc[1][1]);
            acc[2][0] = f2fma(a2, w01, acc[2][0]); acc[2][1] = f2fma(a2, w23, acc[2][1]);
            acc[3][0] = f2fma(a3, w01, acc[3][0]); acc[3][1] = f2fma(a3, w23, acc[3][1]);
        }
    }

    // epilogue: write permuted gx. col c -> (blk=(c&511)>>3, cl=(c>>9)*8+(c&7))
    const int cc = cn0 + tc * 4;
    float bsum[4], res[4];
#pragma unroll
    for (int j = 0; j < 4; j++) bsum[j] = bi[cc + j] + bh[cc + j];
#pragma unroll
    for (int i = 0; i < 4; i++) {
        const int rr = rm0 + tr * 4 + i;
        const int t = rr >> 5;
        const int b = rr & 31;
        res[0] = acc[i][0].x + bsum[0];
        res[1] = acc[i][0].y + bsum[1];
        res[2] = acc[i][1].x + bsum[2];
        res[3] = acc[i][1].y + bsum[3];
#pragma unroll
        for (int j = 0; j < 4; j++) {
            const int c = cc + j;
            const int blk = (c & 511) >> 3;
            const int cl = (c >> 9) * 8 + (c & 7);
            g_gx[dir][blk][t][cl][b] = res[j];
        }
    }
}

// ---------------------------------------------------------------------------
// Phase 2: persistent recurrence. 128 blocks (64/dir), 256 threads (split-k x2).
// R2-proven layouts: Wd[k][c] dup'd float2, Hs[k][b].
// Sync: per-block padded flags (1 per 128B line), st.release + 64-lane poll.
// ---------------------------------------------------------------------------
#define NBLK_PER_DIR 64
#define JB 8
#define NC 32
#define PST 34                     // P row stride (floats), must be even
#define PHALF (32 * PST)           // offset of second k-half partials

#define SM_WD 0                    // float2 Wd[512][32] = 131072 B
#define SM_HS 131072               // float  Hs[512][32] =  65536 B
#define SM_P  196608               // float  P[2][32][34]=   8704 B
#define SM_HO 205312               // float  HO[32][8]   =   1024 B
#define SMEM_TOTAL (205312 + 1024)

__global__ __launch_bounds__(256, 1)
void lstm_persistent_kernel(const float* __restrict__ w_hh_f,
                            const float* __restrict__ w_hh_r,
                            const float* __restrict__ c0,
                            float* __restrict__ out) {
    extern __shared__ __align__(16) char smem_raw[];
    float2* Wd = (float2*)(smem_raw + SM_WD);
    float*  Hs = (float*)(smem_raw + SM_HS);
    float*  P  = (float*)(smem_raw + SM_P);    // [ks][c][b], row stride PST
    float*  HO = (float*)(smem_raw + SM_HO);   // [b][8]

    const int tid = threadIdx.x;
    const int dir = blockIdx.x >> 6;
    const int blk = blockIdx.x & 63;
    const int j0  = blk * JB;
    const float* __restrict__ w = dir ? w_hh_r : w_hh_f;

    // ---- load + duplicate W slice (once): Wd[k][c] ----
    {
        const int c   = tid >> 3;              // 0..31 local gate col
        const int seg = tid & 7;               // k segment of 64
        const int g = c >> 3, u = c & 7;
        const float* wrow = w + (size_t)(g * HID + j0 + u) * HID + seg * 64;
#pragma unroll
        for (int q = 0; q < 16; q++) {
            float4 v = *(const float4*)(wrow + q * 4);
            const int k = seg * 64 + q * 4;
            Wd[(k + 0) * NC + c] = f2(v.x, v.x);
            Wd[(k + 1) * NC + c] = f2(v.y, v.y);
            Wd[(k + 2) * NC + c] = f2(v.z, v.z);
            Wd[(k + 3) * NC + c] = f2(v.w, v.w);
        }
    }

    // ---- pointwise ownership: thread -> (u = tid>>5, b = tid&31) ----
    const int pu = tid >> 5;
    const int pb = tid & 31;
    float creg = c0[((size_t)dir * BATCH + pb) * HID + j0 + pu];

    // ---- GEMM coords: ks = k-half, 8 batch-groups x 16 col-groups ----
    const int ks  = tid >> 7;                  // 0/1
    const int t7  = tid & 127;
    const int bg  = t7 & 7;
    const int cg  = t7 >> 3;
    const int b0  = bg * 4;
    const int cl0 = cg * 2;
    const int k0s = ks * 256;
    float* Pp = P + ks * PHALF;

    const float4* hT4b0 = (const float4*)&g_hT[0][dir][0][0];
    const float4* hT4b1 = (const float4*)&g_hT[1][dir][0][0];
    float4* Hs4 = (float4*)Hs;
    const float* gxbase = &g_gx[dir][blk][0][0][0];
    int* myflag = &g_flags[dir][blk][0];
    int* pollflag = (tid < NBLK_PER_DIR) ? &g_flags[dir][tid][0] : &g_flags[dir][0][0];

    __syncthreads();

    for (int t = 0; t < SEQT; t++) {
        // prefetch gx (coalesced; in flight during the wait). ks=0 only uses it.
        const float* gxp = gxbase + (size_t)t * 1024;
        float4 gxa = *(const float4*)(gxp + cl0 * 32 + b0);
        float4 gxb = *(const float4*)(gxp + (cl0 + 1) * 32 + b0);

        // wait: lane i polls block i's private flag line (no RMW contention)
        if (t > 0 && tid < NBLK_PER_DIR) {
            int v;
            do {
                asm volatile("ld.acquire.gpu.s32 %0, [%1];" : "=r"(v) : "l"(pollflag));
            } while (v < t);
        }
        __syncthreads();

        // stage h (64KB) into Hs[k][b], straight coalesced copy
        const float4* src = (t & 1) ? hT4b1 : hT4b0;
#pragma unroll
        for (int it = 0; it < 16; it++) Hs4[it * 256 + tid] = src[it * 256 + tid];
        __syncthreads();

        // GEMM half: C[b][c] += sum_{k in half} h[b][k]*W[c][k]; lanes = batch pairs
        float2 a00 = f2(0.f, 0.f), a01 = f2(0.f, 0.f);
        float2 a10 = f2(0.f, 0.f), a11 = f2(0.f, 0.f);
#pragma unroll 8
        for (int k = 0; k < 256; k++) {
            const int kk = k0s + k;
            float4 h4 = *(const float4*)&Hs[kk * NC + b0];
            float4 wv = *(const float4*)&Wd[kk * NC + cl0];
            float2 h01 = f2(h4.x, h4.y);
            float2 h23 = f2(h4.z, h4.w);
            float2 w0d = f2(wv.x, wv.y);
            float2 w1d = f2(wv.z, wv.w);
            a00 = f2fma(h01, w0d, a00);
            a01 = f2fma(h01, w1d, a01);
            a10 = f2fma(h23, w0d, a10);
            a11 = f2fma(h23, w1d, a11);
        }
        if (ks == 0) {       // fold gx into the ks=0 partial
            a00.x += gxa.x; a00.y += gxa.y;
            a01.x += gxb.x; a01.y += gxb.y;
            a10.x += gxa.z; a10.y += gxa.w;
            a11.x += gxb.z; a11.y += gxb.w;
        }
        *(float2*)&Pp[(cl0)     * PST + b0]     = a00;
        *(float2*)&Pp[(cl0 + 1) * PST + b0]     = a01;
        *(float2*)&Pp[(cl0)     * PST + b0 + 2] = a10;
        *(float2*)&Pp[(cl0 + 1) * PST + b0 + 2] = a11;
        __syncthreads();

        // pointwise: 1 item/thread; sum the two k-half partials
        float* hdst = (t & 1) ? (float*)&g_hT[0][dir][0][0]
                              : (float*)&g_hT[1][dir][0][0];
        {
            const float pi = P[(pu)      * PST + pb] + P[PHALF + (pu)      * PST + pb];
            const float pf = P[(8 + pu)  * PST + pb] + P[PHALF + (8 + pu)  * PST + pb];
            const float pg = P[(16 + pu) * PST + pb] + P[PHALF + (16 + pu) * PST + pb];
            const float po = P[(24 + pu) * PST + pb] + P[PHALF + (24 + pu) * PST + pb];
            const float iv = sigf(pi);
            const float fv = sigf(pf);
            const float gv = tanhx(pg);
            const float ov = sigf(po);
            creg = fv * creg + iv * gv;
            const float hnew = ov * tanhx(creg);
            hdst[(j0 + pu) * BATCH + pb] = hnew;     // coalesced per warp
            HO[pb * 8 + pu] = hnew;
            if (t == SEQT - 1) {
                out[OUT_HN + ((size_t)dir * BATCH + pb) * HID + j0 + pu] = hnew;
                out[OUT_CN + ((size_t)dir * BATCH + pb) * HID + j0 + pu] = creg;
            }
        }
        __syncthreads();   // hdst + HO visible

        // signal completion of step t FIRST (single release store, private line)
        if (tid == 0) {
            asm volatile("st.release.gpu.s32 [%0], %1;" :: "l"(myflag), "r"(t + 1));
        }

        // coalesced out write (128 threads x float2) — off the critical path
        if (tid < 128) {
            const int tout = dir ? (SEQT - 1 - t) : t;
            const int ob = tid >> 2;
            const int ou = (tid & 3) * 2;
            float2 v = *(const float2*)&HO[ob * 8 + ou];
            *(float2*)&out[((size_t)ob * SEQT + tout) * (2 * HID) + dir * HID + j0 + ou] = v;
        }
    }
}

// ---------------------------------------------------------------------------
// Launch
// ---------------------------------------------------------------------------
extern "C" void kernel_launch(void* const* d_in, const int* in_sizes, int n_in,
                              void* d_out, int out_size) {
    const float* x      = (const float*)d_in[0];
    const float* h0     = (const float*)d_in[1];
    const float* c0     = (const float*)d_in[2];
    const float* w_ih_f = (const float*)d_in[3];
    const float* w_hh_f = (const float*)d_in[4];
    const float* b_ih_f = (const float*)d_in[5];
    const float* b_hh_f = (const float*)d_in[6];
    const float* w_ih_r = (const float*)d_in[7];
    const float* w_hh_r = (const float*)d_in[8];
    const float* b_ih_r = (const float*)d_in[9];
    const float* b_hh_r = (const float*)d_in[10];
    float* out = (float*)d_out;

    cudaFuncSetAttribute(lstm_persistent_kernel,
                         cudaFuncAttributeMaxDynamicSharedMemorySize, SMEM_TOTAL);

    dim3 ggrid(G4 / BN, (SEQT * BATCH) / BM, 2);   // (32, 256, 2)
    gemm_ih_kernel<<<ggrid, 256>>>(x, h0, w_ih_f, w_ih_r,
                                   b_ih_f, b_hh_f, b_ih_r, b_hh_r);

    lstm_persistent_kernel<<<2 * NBLK_PER_DIR, 256, SMEM_TOTAL>>>(
        w_hh_f, w_hh_r, c0, out);
}

// round 9
// speedup vs baseline: 1.0976x; 1.0976x over previous
#include <cuda_runtime.h>
#include <math.h>

#define BATCH 32
#define SEQT  512
#define HID   512
#define G4    2048   // 4*HID

// out layout (fp32): out[B][T][2H] @0, h_n[2][B][H] @16777216, c_n @16809984
#define OUT_HN 16777216
#define OUT_CN 16809984

// ---------------------------------------------------------------------------
// Device globals (allocation-free scratch), 256B-aligned for vector access.
// ---------------------------------------------------------------------------
// gx permuted per consumer block: [dir][blk(64)][t(512)][cl(32)][b(32)]
__device__ __align__(256) float g_gx[2][64][SEQT][32][32];
__device__ __align__(256) float g_hT[2][2][HID][BATCH];   // [parity][dir][unit][batch]
__device__ __align__(256) int   g_arrive[2];              // per-dir step counters

// ---------------------------------------------------------------------------
// Packed fp32x2 FMA (Blackwell FFMA2; only reachable via PTX)
// ---------------------------------------------------------------------------
__device__ __forceinline__ float2 f2fma(float2 a, float2 b, float2 c) {
    unsigned long long ra = *reinterpret_cast<unsigned long long*>(&a);
    unsigned long long rb = *reinterpret_cast<unsigned long long*>(&b);
    unsigned long long rc = *reinterpret_cast<unsigned long long*>(&c);
    unsigned long long rd;
    asm("fma.rn.f32x2 %0, %1, %2, %3;" : "=l"(rd) : "l"(ra), "l"(rb), "l"(rc));
    return *reinterpret_cast<float2*>(&rd);
}
__device__ __forceinline__ float2 f2(float x, float y) { return make_float2(x, y); }

__device__ __forceinline__ float sigf(float x) { return 1.0f / (1.0f + __expf(-x)); }
__device__ __forceinline__ float tanhx(float x) { return 2.0f / (1.0f + __expf(-2.0f * x)) - 1.0f; }

// ---------------------------------------------------------------------------
// Phase 1: gx = x @ W_ih^T + biases (written permuted). Init of h/counters is
// embedded. BM=BN=64, BK=16, 256 thr, 4x4 microtile, dup'd-A f32x2.
// ---------------------------------------------------------------------------
#define BM 64
#define BN 64
#define BK 16

__global__ __launch_bounds__(256) void gemm_ih_kernel(
        const float* __restrict__ x,
        const float* __restrict__ h0,
        const float* __restrict__ w_f, const float* __restrict__ w_r,
        const float* __restrict__ bi_f, const float* __restrict__ bh_f,
        const float* __restrict__ bi_r, const float* __restrict__ bh_r) {
    const int tid = threadIdx.x;

    // ---- embedded init (h0 -> g_hT[0], counters) ----
    {
        const int gid = (blockIdx.z * gridDim.y + blockIdx.y) * gridDim.x + blockIdx.x;
        if (gid < 128) {
            const int idx = gid * 256 + tid;     // 0..32767
            const int dirI = idx >> 14;
            const int bI = (idx >> 9) & 31;
            const int jI = idx & 511;
            g_hT[0][dirI][jI][bI] = h0[idx];
        }
        if (gid == 0 && tid < 2) g_arrive[tid] = 0;
    }

    const int dir = blockIdx.z;
    const float* __restrict__ w  = dir ? w_r  : w_f;
    const float* __restrict__ bi = dir ? bi_r : bi_f;
    const float* __restrict__ bh = dir ? bh_r : bh_f;

    const int rm0 = blockIdx.y * BM;   // rows over T*B (row = t*32+b)
    const int cn0 = blockIdx.x * BN;   // cols over 4H

    __shared__ __align__(16) float2 Asd[BK][BM + 2];   // A rows, duplicated lanes
    __shared__ __align__(16) float  Ws[BK][BN + 4];

    const int tr = tid / 16;           // 0..15 row group
    const int tc = tid % 16;           // 0..15 col group

    const int l_row = tid >> 2;        // 0..63
    const int l_k4  = (tid & 3) << 2;  // 0,4,8,12

    const int r  = rm0 + l_row;
    int       tt = r >> 5;
    const int bb = r & 31;
    if (dir) tt = (SEQT - 1) - tt;
    const float* a_ptr = x + ((size_t)bb * SEQT + tt) * HID;
    const float* w_ptr = w + (size_t)(cn0 + l_row) * HID;

    float2 acc[4][2];
#pragma unroll
    for (int i = 0; i < 4; i++) { acc[i][0] = f2(0.f, 0.f); acc[i][1] = f2(0.f, 0.f); }

    for (int k0 = 0; k0 < HID; k0 += BK) {
        float4 av = *(const float4*)(a_ptr + k0 + l_k4);
        float4 wv = *(const float4*)(w_ptr + k0 + l_k4);
        __syncthreads();
        Asd[l_k4 + 0][l_row] = f2(av.x, av.x);
        Asd[l_k4 + 1][l_row] = f2(av.y, av.y);
        Asd[l_k4 + 2][l_row] = f2(av.z, av.z);
        Asd[l_k4 + 3][l_row] = f2(av.w, av.w);
        Ws[l_k4 + 0][l_row] = wv.x;
        Ws[l_k4 + 1][l_row] = wv.y;
        Ws[l_k4 + 2][l_row] = wv.z;
        Ws[l_k4 + 3][l_row] = wv.w;
        __syncthreads();
#pragma unroll
        for (int kk = 0; kk < BK; kk++) {
            float4 ad0 = *(const float4*)&Asd[kk][tr * 4];
            float4 ad1 = *(const float4*)&Asd[kk][tr * 4 + 2];
            float4 w4  = *(const float4*)&Ws[kk][tc * 4];
            float2 w01 = f2(w4.x, w4.y);
            float2 w23 = f2(w4.z, w4.w);
            float2 a0 = f2(ad0.x, ad0.y);
            float2 a1 = f2(ad0.z, ad0.w);
            float2 a2 = f2(ad1.x, ad1.y);
            float2 a3 = f2(ad1.z, ad1.w);
            acc[0][0] = f2fma(a0, w01, acc[0][0]); acc[0][1] = f2fma(a0, w23, acc[0][1]);
            acc[1][0] = f2fma(a1, w01, acc[1][0]); acc[1][1] = f2fma(a1, w23, acc[1][1]);
            acc[2][0] = f2fma(a2, w01, acc[2][0]); acc[2][1] = f2fma(a2, w23, acc[2][1]);
            acc[3][0] = f2fma(a3, w01, acc[3][0]); acc[3][1] = f2fma(a3, w23, acc[3][1]);
        }
    }

    // epilogue: write permuted gx. col c -> (blk=(c&511)>>3, cl=(c>>9)*8+(c&7))
    const int cc = cn0 + tc * 4;
    float bsum[4], res[4];
#pragma unroll
    for (int j = 0; j < 4; j++) bsum[j] = bi[cc + j] + bh[cc + j];
#pragma unroll
    for (int i = 0; i < 4; i++) {
        const int rr = rm0 + tr * 4 + i;
        const int t = rr >> 5;
        const int b = rr & 31;
        res[0] = acc[i][0].x + bsum[0];
        res[1] = acc[i][0].y + bsum[1];
        res[2] = acc[i][1].x + bsum[2];
        res[3] = acc[i][1].y + bsum[3];
#pragma unroll
        for (int j = 0; j < 4; j++) {
            const int c = cc + j;
            const int blk = (c & 511) >> 3;
            const int cl = (c >> 9) * 8 + (c & 7);
            g_gx[dir][blk][t][cl][b] = res[j];
        }
    }
}

// ---------------------------------------------------------------------------
// Phase 2: persistent recurrence. 128 blocks (64/dir), 256 threads.
// W-broadcast GEMM: lane = batch; warp owns 8 cols x one k-half.
//   h: LDS.32 Hs[k][lane] (coalesced), W: LDS.128 Ws[c][k] (broadcast, 16B).
// Sync: R7 counter (measured best). P is scalar-access only (stride 33).
// ---------------------------------------------------------------------------
#define NBLK_PER_DIR 64
#define JB 8
#define NC 32
#define WST 512                    // Ws row stride (floats); broadcast-only reads
#define PST 33                     // P row stride (floats); scalar access only
#define PHALF (32 * PST)           // second k-half partial offset

#define SM_WS 0                    // float Ws[32][512] = 65536 B
#define SM_HS 65536                // float Hs[512][32] = 65536 B
#define SM_P  131072               // float P[2][32][33] = 8448 B
#define SM_HO 139520               // float HO[32][8]    = 1024 B
#define SMEM_TOTAL (139520 + 1024)

__global__ __launch_bounds__(256, 1)
void lstm_persistent_kernel(const float* __restrict__ w_hh_f,
                            const float* __restrict__ w_hh_r,
                            const float* __restrict__ c0,
                            float* __restrict__ out) {
    extern __shared__ __align__(16) char smem_raw[];
    float* Ws = (float*)(smem_raw + SM_WS);    // [c][k]
    float* Hs = (float*)(smem_raw + SM_HS);    // [k][b]
    float* P  = (float*)(smem_raw + SM_P);     // [ks][c][b], stride PST
    float* HO = (float*)(smem_raw + SM_HO);    // [b][8]

    const int tid = threadIdx.x;
    const int dir = blockIdx.x >> 6;
    const int blk = blockIdx.x & 63;
    const int j0  = blk * JB;
    const float* __restrict__ w = dir ? w_hh_r : w_hh_f;
    int* arrive = &g_arrive[dir];

    // ---- load W slice (once): Ws[c][k] plain ----
    {
        const int c   = tid >> 3;              // 0..31 local gate col
        const int seg = tid & 7;               // k segment of 64
        const int g = c >> 3, u = c & 7;
        const float* wrow = w + (size_t)(g * HID + j0 + u) * HID + seg * 64;
        float* wdst = Ws + c * WST + seg * 64;
#pragma unroll
        for (int q = 0; q < 16; q++)
            *(float4*)(wdst + q * 4) = *(const float4*)(wrow + q * 4);
    }

    // ---- pointwise ownership: thread -> (u = tid>>5, b = tid&31) ----
    const int pu = tid >> 5;
    const int pb = tid & 31;
    float creg = c0[((size_t)dir * BATCH + pb) * HID + j0 + pu];

    // ---- GEMM coords: warp -> (ks, col group of 8); lane = batch ----
    const int wid  = tid >> 5;                 // 0..7
    const int lane = tid & 31;
    const int ks   = wid >> 2;                 // 0/1 k-half
    const int cg8  = (wid & 3) * 8;            // first of 8 local cols
    const int k0s  = ks * 256;

    const float4* hT4b0 = (const float4*)&g_hT[0][dir][0][0];
    const float4* hT4b1 = (const float4*)&g_hT[1][dir][0][0];
    float4* Hs4 = (float4*)Hs;
    const float* gxbase = &g_gx[dir][blk][0][0][0];

    __syncthreads();

    for (int t = 0; t < SEQT; t++) {
        // prefetch gx (coalesced; in flight during the wait) — ks=0 warps only
        const float* gxp = gxbase + (size_t)t * 1024;
        float gxr[8];
#pragma unroll
        for (int c8 = 0; c8 < 8; c8++)
            gxr[c8] = (ks == 0) ? gxp[(cg8 + c8) * 32 + lane] : 0.f;

        // wait for all same-dir blocks to finish step t-1 (counter scheme)
        if (t > 0 && tid == 0) {
            const int target = NBLK_PER_DIR * t;
            int v;
            do {
                asm volatile("ld.acquire.gpu.s32 %0, [%1];" : "=r"(v) : "l"(arrive));
            } while (v < target);
        }
        __syncthreads();

        // stage h (64KB) into Hs[k][b], straight coalesced copy
        const float4* src = (t & 1) ? hT4b1 : hT4b0;
#pragma unroll
        for (int it = 0; it < 16; it++) Hs4[it * 256 + tid] = src[it * 256 + tid];
        __syncthreads();

        // GEMM: this warp: cols [cg8, cg8+8), k in [k0s, k0s+256), all 32 b (lane)
        float2 acc[8];
#pragma unroll
        for (int c8 = 0; c8 < 8; c8++) acc[c8] = f2(0.f, 0.f);
#pragma unroll 4
        for (int ch = 0; ch < 64; ch++) {
            const int kq = k0s + ch * 4;
            const float h0 = Hs[(kq + 0) * NC + lane];
            const float h1 = Hs[(kq + 1) * NC + lane];
            const float h2 = Hs[(kq + 2) * NC + lane];
            const float h3 = Hs[(kq + 3) * NC + lane];
            const float2 hA = f2(h0, h1);
            const float2 hB = f2(h2, h3);
#pragma unroll
            for (int c8 = 0; c8 < 8; c8++) {
                const float4 w4 = *(const float4*)&Ws[(cg8 + c8) * WST + kq];
                acc[c8] = f2fma(hA, f2(w4.x, w4.y), acc[c8]);
                acc[c8] = f2fma(hB, f2(w4.z, w4.w), acc[c8]);
            }
        }
        // write partials (scalar stores; coalesced per c: lanes consecutive)
#pragma unroll
        for (int c8 = 0; c8 < 8; c8++) {
            P[ks * PHALF + (cg8 + c8) * PST + lane] = acc[c8].x + acc[c8].y + gxr[c8];
        }
        __syncthreads();

        // pointwise: 1 item/thread; sum the two k-half partials
        float* hdst = (t & 1) ? (float*)&g_hT[0][dir][0][0]
                              : (float*)&g_hT[1][dir][0][0];
        {
            const float pi = P[(pu)      * PST + pb] + P[PHALF + (pu)      * PST + pb];
            const float pf = P[(8 + pu)  * PST + pb] + P[PHALF + (8 + pu)  * PST + pb];
            const float pg = P[(16 + pu) * PST + pb] + P[PHALF + (16 + pu) * PST + pb];
            const float po = P[(24 + pu) * PST + pb] + P[PHALF + (24 + pu) * PST + pb];
            const float iv = sigf(pi);
            const float fv = sigf(pf);
            const float gv = tanhx(pg);
            const float ov = sigf(po);
            creg = fv * creg + iv * gv;
            const float hnew = ov * tanhx(creg);
            hdst[(j0 + pu) * BATCH + pb] = hnew;     // coalesced per warp
            HO[pb * 8 + pu] = hnew;
            if (t == SEQT - 1) {
                out[OUT_HN + ((size_t)dir * BATCH + pb) * HID + j0 + pu] = hnew;
                out[OUT_CN + ((size_t)dir * BATCH + pb) * HID + j0 + pu] = creg;
            }
        }
        __syncthreads();   // hdst + HO visible

        // coalesced out write (128 threads x float2)
        if (tid < 128) {
            const int tout = dir ? (SEQT - 1 - t) : t;
            const int ob = tid >> 2;
            const int ou = (tid & 3) * 2;
            float2 v = *(const float2*)&HO[ob * 8 + ou];
            *(float2*)&out[((size_t)ob * SEQT + tout) * (2 * HID) + dir * HID + j0 + ou] = v;
        }

        // signal completion of step t
        if (tid == 0) {
            int dummy;
            asm volatile("atom.release.gpu.add.s32 %0, [%1], 1;"
                         : "=r"(dummy) : "l"(arrive));
        }
    }
}

// ---------------------------------------------------------------------------
// Launch
// ---------------------------------------------------------------------------
extern "C" void kernel_launch(void* const* d_in, const int* in_sizes, int n_in,
                              void* d_out, int out_size) {
    const float* x      = (const float*)d_in[0];
    const float* h0     = (const float*)d_in[1];
    const float* c0     = (const float*)d_in[2];
    const float* w_ih_f = (const float*)d_in[3];
    const float* w_hh_f = (const float*)d_in[4];
    const float* b_ih_f = (const float*)d_in[5];
    const float* b_hh_f = (const float*)d_in[6];
    const float* w_ih_r = (const float*)d_in[7];
    const float* w_hh_r = (const float*)d_in[8];
    const float* b_ih_r = (const float*)d_in[9];
    const float* b_hh_r = (const float*)d_in[10];
    float* out = (float*)d_out;

    cudaFuncSetAttribute(lstm_persistent_kernel,
                         cudaFuncAttributeMaxDynamicSharedMemorySize, SMEM_TOTAL);

    dim3 ggrid(G4 / BN, (SEQT * BATCH) / BM, 2);   // (32, 256, 2)
    gemm_ih_kernel<<<ggrid, 256>>>(x, h0, w_ih_f, w_ih_r,
                                   b_ih_f, b_hh_f, b_ih_r, b_hh_r);

    lstm_persistent_kernel<<<2 * NBLK_PER_DIR, 256, SMEM_TOTAL>>>(
        w_hh_f, w_hh_r, c0, out);
}

// round 10
// speedup vs baseline: 1.2043x; 1.0973x over previous
#include <cuda_runtime.h>
#include <math.h>

#define BATCH 32
#define SEQT  512
#define HID   512
#define G4    2048   // 4*HID

// out layout (fp32): out[B][T][2H] @0, h_n[2][B][H] @16777216, c_n @16809984
#define OUT_HN 16777216
#define OUT_CN 16809984

// ---------------------------------------------------------------------------
// Device globals (allocation-free scratch), 256B-aligned for vector access.
// ---------------------------------------------------------------------------
// gx permuted per consumer block: [dir][blk(64)][t(512)][cl(32)][b(32)]
__device__ __align__(256) float g_gx[2][64][SEQT][32][32];
__device__ __align__(256) float g_hB[2][2][BATCH][HID];   // [parity][dir][batch][unit]
__device__ __align__(256) int   g_arrive[2];              // per-dir step counters

// ---------------------------------------------------------------------------
// Packed fp32x2 FMA (Blackwell FFMA2; only reachable via PTX)
// ---------------------------------------------------------------------------
__device__ __forceinline__ float2 f2fma(float2 a, float2 b, float2 c) {
    unsigned long long ra = *reinterpret_cast<unsigned long long*>(&a);
    unsigned long long rb = *reinterpret_cast<unsigned long long*>(&b);
    unsigned long long rc = *reinterpret_cast<unsigned long long*>(&c);
    unsigned long long rd;
    asm("fma.rn.f32x2 %0, %1, %2, %3;" : "=l"(rd) : "l"(ra), "l"(rb), "l"(rc));
    return *reinterpret_cast<float2*>(&rd);
}
__device__ __forceinline__ float2 f2(float x, float y) { return make_float2(x, y); }

__device__ __forceinline__ float sigf(float x) { return 1.0f / (1.0f + __expf(-x)); }
__device__ __forceinline__ float tanhx(float x) { return 2.0f / (1.0f + __expf(-2.0f * x)) - 1.0f; }

// ---------------------------------------------------------------------------
// Phase 1: gx = x @ W_ih^T + biases (written permuted). Init of h/counters is
// embedded. BM=BN=64, BK=16, 256 thr, 4x4 microtile, dup'd-A f32x2 (unchanged).
// ---------------------------------------------------------------------------
#define BM 64
#define BN 64
#define BK 16

__global__ __launch_bounds__(256) void gemm_ih_kernel(
        const float* __restrict__ x,
        const float* __restrict__ h0,
        const float* __restrict__ w_f, const float* __restrict__ w_r,
        const float* __restrict__ bi_f, const float* __restrict__ bh_f,
        const float* __restrict__ bi_r, const float* __restrict__ bh_r) {
    const int tid = threadIdx.x;

    // ---- embedded init (h0 -> g_hB[0] (identical linear layout), counters) ----
    {
        const int gid = (blockIdx.z * gridDim.y + blockIdx.y) * gridDim.x + blockIdx.x;
        if (gid < 128) {
            const int idx = gid * 256 + tid;     // 0..32767
            (&g_hB[0][0][0][0])[idx] = h0[idx];  // [dir][b][j] matches h0 layout
        }
        if (gid == 0 && tid < 2) g_arrive[tid] = 0;
    }

    const int dir = blockIdx.z;
    const float* __restrict__ w  = dir ? w_r  : w_f;
    const float* __restrict__ bi = dir ? bi_r : bi_f;
    const float* __restrict__ bh = dir ? bh_r : bh_f;

    const int rm0 = blockIdx.y * BM;   // rows over T*B (row = t*32+b)
    const int cn0 = blockIdx.x * BN;   // cols over 4H

    __shared__ __align__(16) float2 Asd[BK][BM + 2];   // A rows, duplicated lanes
    __shared__ __align__(16) float  Ws[BK][BN + 4];

    const int tr = tid / 16;           // 0..15 row group
    const int tc = tid % 16;           // 0..15 col group

    const int l_row = tid >> 2;        // 0..63
    const int l_k4  = (tid & 3) << 2;  // 0,4,8,12

    const int r  = rm0 + l_row;
    int       tt = r >> 5;
    const int bb = r & 31;
    if (dir) tt = (SEQT - 1) - tt;
    const float* a_ptr = x + ((size_t)bb * SEQT + tt) * HID;
    const float* w_ptr = w + (size_t)(cn0 + l_row) * HID;

    float2 acc[4][2];
#pragma unroll
    for (int i = 0; i < 4; i++) { acc[i][0] = f2(0.f, 0.f); acc[i][1] = f2(0.f, 0.f); }

    for (int k0 = 0; k0 < HID; k0 += BK) {
        float4 av = *(const float4*)(a_ptr + k0 + l_k4);
        float4 wv = *(const float4*)(w_ptr + k0 + l_k4);
        __syncthreads();
        Asd[l_k4 + 0][l_row] = f2(av.x, av.x);
        Asd[l_k4 + 1][l_row] = f2(av.y, av.y);
        Asd[l_k4 + 2][l_row] = f2(av.z, av.z);
        Asd[l_k4 + 3][l_row] = f2(av.w, av.w);
        Ws[l_k4 + 0][l_row] = wv.x;
        Ws[l_k4 + 1][l_row] = wv.y;
        Ws[l_k4 + 2][l_row] = wv.z;
        Ws[l_k4 + 3][l_row] = wv.w;
        __syncthreads();
#pragma unroll
        for (int kk = 0; kk < BK; kk++) {
            float4 ad0 = *(const float4*)&Asd[kk][tr * 4];
            float4 ad1 = *(const float4*)&Asd[kk][tr * 4 + 2];
            float4 w4  = *(const float4*)&Ws[kk][tc * 4];
            float2 w01 = f2(w4.x, w4.y);
            float2 w23 = f2(w4.z, w4.w);
            float2 a0 = f2(ad0.x, ad0.y);
            float2 a1 = f2(ad0.z, ad0.w);
            float2 a2 = f2(ad1.x, ad1.y);
            float2 a3 = f2(ad1.z, ad1.w);
            acc[0][0] = f2fma(a0, w01, acc[0][0]); acc[0][1] = f2fma(a0, w23, acc[0][1]);
            acc[1][0] = f2fma(a1, w01, acc[1][0]); acc[1][1] = f2fma(a1, w23, acc[1][1]);
            acc[2][0] = f2fma(a2, w01, acc[2][0]); acc[2][1] = f2fma(a2, w23, acc[2][1]);
            acc[3][0] = f2fma(a3, w01, acc[3][0]); acc[3][1] = f2fma(a3, w23, acc[3][1]);
        }
    }

    // epilogue: write permuted gx. col c -> (blk=(c&511)>>3, cl=(c>>9)*8+(c&7))
    const int cc = cn0 + tc * 4;
    float bsum[4], res[4];
#pragma unroll
    for (int j = 0; j < 4; j++) bsum[j] = bi[cc + j] + bh[cc + j];
#pragma unroll
    for (int i = 0; i < 4; i++) {
        const int rr = rm0 + tr * 4 + i;
        const int t = rr >> 5;
        const int b = rr & 31;
        res[0] = acc[i][0].x + bsum[0];
        res[1] = acc[i][0].y + bsum[1];
        res[2] = acc[i][1].x + bsum[2];
        res[3] = acc[i][1].y + bsum[3];
#pragma unroll
        for (int j = 0; j < 4; j++) {
            const int c = cc + j;
            const int blk = (c & 511) >> 3;
            const int cl = (c >> 9) * 8 + (c & 7);
            g_gx[dir][blk][t][cl][b] = res[j];
        }
    }
}

// ---------------------------------------------------------------------------
// Phase 2: persistent recurrence. 128 blocks (64/dir), 256 threads.
// W-in-registers GEMM: warp = (batch-half, gate) -> 8 cols x 16 batches;
// lane = k mod 32; wreg[8][8] float2 holds the warp's W slice for all 512 steps.
// h read: 2 coalesced LDS.32 per jp. k-reduction: value-halving SHFL butterfly.
// ---------------------------------------------------------------------------
#define NBLK_PER_DIR 64
#define JB 8
#define PST 33                     // P row stride (floats); scalar access only

#define SM_HS 0                    // float Hs[32][512] = 65536 B
#define SM_P  65536                // float P[32][33]   =  4224 B
#define SM_HO 69760                // float HO[32][8]   =  1024 B
#define SMEM_TOTAL (69760 + 1024)

__global__ __launch_bounds__(256, 1)
void lstm_persistent_kernel(const float* __restrict__ w_hh_f,
                            const float* __restrict__ w_hh_r,
                            const float* __restrict__ c0,
                            float* __restrict__ out) {
    extern __shared__ __align__(16) char smem_raw[];
    float* Hs = (float*)(smem_raw + SM_HS);    // [b][k], stride 512
    float* P  = (float*)(smem_raw + SM_P);     // [c_local][b], stride PST
    float* HO = (float*)(smem_raw + SM_HO);    // [b][8]

    const int tid = threadIdx.x;
    const int dir = blockIdx.x >> 6;
    const int blk = blockIdx.x & 63;
    const int j0  = blk * JB;
    const float* __restrict__ w = dir ? w_hh_r : w_hh_f;
    int* arrive = &g_arrive[dir];

    const int wid  = tid >> 5;                 // 0..7
    const int lane = tid & 31;

    // ---- GEMM warp coords: hb = batch half, cq = gate; lane = k mod 32 ----
    const int hb = wid >> 2;                   // 0/1
    const int cq = wid & 3;                    // gate 0..3

    // ---- W registers: wreg[c8][jp] = (W[c][64jp+lane], W[c][64jp+32+lane]) ----
    float2 wreg[8][8];
#pragma unroll
    for (int c8 = 0; c8 < 8; c8++) {
        const float* wr = w + (size_t)(cq * HID + j0 + c8) * HID;
#pragma unroll
        for (int jp = 0; jp < 8; jp++)
            wreg[c8][jp] = f2(wr[jp * 64 + lane], wr[jp * 64 + 32 + lane]);
    }

    // reduction lane constants: final col owned = cmap, replicated over lane&3
    const bool hi16 = (lane & 16) != 0;
    const bool hi8  = (lane & 8)  != 0;
    const bool hi4  = (lane & 4)  != 0;
    const int  cmap = ((lane >> 4) & 1) * 4 + ((lane >> 3) & 1) * 2 + ((lane >> 2) & 1);
    float* pdst = &P[(cq * 8 + cmap) * PST + hb * 16];

    // ---- pointwise ownership: thread -> (u = wid, b = lane) ----
    const int pu = wid;
    const int pb = lane;
    float creg = c0[((size_t)dir * BATCH + pb) * HID + j0 + pu];

    const float4* hB0 = (const float4*)&g_hB[0][dir][0][0];
    const float4* hB1 = (const float4*)&g_hB[1][dir][0][0];
    float4* Hs4 = (float4*)Hs;
    const float* gxbase = &g_gx[dir][blk][0][0][0];

    __syncthreads();

    for (int t = 0; t < SEQT; t++) {
        // prefetch gx (pointwise mapping; coalesced; in flight during the wait)
        const float* gxp = gxbase + (size_t)t * 1024;
        float gxr0 = gxp[(pu)      * 32 + pb];
        float gxr1 = gxp[(8 + pu)  * 32 + pb];
        float gxr2 = gxp[(16 + pu) * 32 + pb];
        float gxr3 = gxp[(24 + pu) * 32 + pb];

        // wait for all same-dir blocks to finish step t-1
        if (t > 0 && tid == 0) {
            const int target = NBLK_PER_DIR * t;
            int v;
            do {
                asm volatile("ld.acquire.gpu.s32 %0, [%1];" : "=r"(v) : "l"(arrive));
            } while (v < target);
        }
        __syncthreads();

        // stage h (64KB) into Hs[b][k] — straight linear coalesced copy
        const float4* src = (t & 1) ? hB1 : hB0;
#pragma unroll
        for (int it = 0; it < 16; it++) Hs4[it * 256 + tid] = src[it * 256 + tid];
        __syncthreads();

        // GEMM: per batch: 16 LDS + 64 FFMA2 + butterfly reduce + 1 STS
        const float* hbase = Hs + (hb * 16) * 512 + lane;
        for (int bi = 0; bi < 16; bi++) {
            const float* hp = hbase + bi * 512;
            float2 a0 = f2(0.f, 0.f), a1 = f2(0.f, 0.f), a2 = f2(0.f, 0.f), a3 = f2(0.f, 0.f);
            float2 a4 = f2(0.f, 0.f), a5 = f2(0.f, 0.f), a6 = f2(0.f, 0.f), a7 = f2(0.f, 0.f);
#pragma unroll
            for (int jp = 0; jp < 8; jp++) {
                float2 hv = f2(hp[jp * 64], hp[jp * 64 + 32]);
                a0 = f2fma(hv, wreg[0][jp], a0);
                a1 = f2fma(hv, wreg[1][jp], a1);
                a2 = f2fma(hv, wreg[2][jp], a2);
                a3 = f2fma(hv, wreg[3][jp], a3);
                a4 = f2fma(hv, wreg[4][jp], a4);
                a5 = f2fma(hv, wreg[5][jp], a5);
                a6 = f2fma(hv, wreg[6][jp], a6);
                a7 = f2fma(hv, wreg[7][jp], a7);
            }
            float v0 = a0.x + a0.y, v1 = a1.x + a1.y, v2 = a2.x + a2.y, v3 = a3.x + a3.y;
            float v4 = a4.x + a4.y, v5 = a5.x + a5.y, v6 = a6.x + a6.y, v7 = a7.x + a7.y;

            // value-halving butterfly over lanes (k-residues)
            // stage xor16: keep 4 (col bit2 = lane bit4)
            float k0 = hi16 ? v4 : v0,  s0 = hi16 ? v0 : v4;
            float k1 = hi16 ? v5 : v1,  s1 = hi16 ? v1 : v5;
            float k2 = hi16 ? v6 : v2,  s2 = hi16 ? v2 : v6;
            float k3 = hi16 ? v7 : v3,  s3 = hi16 ? v3 : v7;
            k0 += __shfl_xor_sync(0xffffffffu, s0, 16);
            k1 += __shfl_xor_sync(0xffffffffu, s1, 16);
            k2 += __shfl_xor_sync(0xffffffffu, s2, 16);
            k3 += __shfl_xor_sync(0xffffffffu, s3, 16);
            // stage xor8: keep 2 (col bit1 = lane bit3)
            float m0 = hi8 ? k2 : k0,  t0 = hi8 ? k0 : k2;
            float m1 = hi8 ? k3 : k1,  t1 = hi8 ? k1 : k3;
            m0 += __shfl_xor_sync(0xffffffffu, t0, 8);
            m1 += __shfl_xor_sync(0xffffffffu, t1, 8);
            // stage xor4: keep 1 (col bit0 = lane bit2)
            float m = hi4 ? m1 : m0,  u = hi4 ? m0 : m1;
            m += __shfl_xor_sync(0xffffffffu, u, 4);
            // remaining lane bits 1,0: plain allreduce
            m += __shfl_xor_sync(0xffffffffu, m, 2);
            m += __shfl_xor_sync(0xffffffffu, m, 1);
            if ((lane & 3) == 0) pdst[bi] = m;
        }
        __syncthreads();

        // pointwise: 1 item/thread
        {
            const float pi = P[(pu)      * PST + pb] + gxr0;
            const float pf = P[(8 + pu)  * PST + pb] + gxr1;
            const float pg = P[(16 + pu) * PST + pb] + gxr2;
            const float po = P[(24 + pu) * PST + pb] + gxr3;
            const float iv = sigf(pi);
            const float fv = sigf(pf);
            const float gv = tanhx(pg);
            const float ov = sigf(po);
            creg = fv * creg + iv * gv;
            const float hnew = ov * tanhx(creg);
            HO[pb * 8 + pu] = hnew;
            if (t == SEQT - 1) {
                out[OUT_HN + ((size_t)dir * BATCH + pb) * HID + j0 + pu] = hnew;
                out[OUT_CN + ((size_t)dir * BATCH + pb) * HID + j0 + pu] = creg;
            }
        }
        __syncthreads();   // HO visible

        // 128 threads: write next-h (coalesced) + out from HO bounce
        if (tid < 128) {
            const int ob = tid >> 2;
            const int ou = (tid & 3) * 2;
            float2 v = *(const float2*)&HO[ob * 8 + ou];
            float* hdst = (t & 1) ? (float*)&g_hB[0][dir][0][0]
                                  : (float*)&g_hB[1][dir][0][0];
            *(float2*)&hdst[ob * HID + j0 + ou] = v;
            const int tout = dir ? (SEQT - 1 - t) : t;
            *(float2*)&out[((size_t)ob * SEQT + tout) * (2 * HID) + dir * HID + j0 + ou] = v;
        }
        __syncthreads();   // h stores issued block-wide before the release

        // signal completion of step t
        if (tid == 0) {
            int dummy;
            asm volatile("atom.release.gpu.add.s32 %0, [%1], 1;"
                         : "=r"(dummy) : "l"(arrive));
        }
    }
}

// ---------------------------------------------------------------------------
// Launch
// ---------------------------------------------------------------------------
extern "C" void kernel_launch(void* const* d_in, const int* in_sizes, int n_in,
                              void* d_out, int out_size) {
    const float* x      = (const float*)d_in[0];
    const float* h0     = (const float*)d_in[1];
    const float* c0     = (const float*)d_in[2];
    const float* w_ih_f = (const float*)d_in[3];
    const float* w_hh_f = (const float*)d_in[4];
    const float* b_ih_f = (const float*)d_in[5];
    const float* b_hh_f = (const float*)d_in[6];
    const float* w_ih_r = (const float*)d_in[7];
    const float* w_hh_r = (const float*)d_in[8];
    const float* b_ih_r = (const float*)d_in[9];
    const float* b_hh_r = (const float*)d_in[10];
    float* out = (float*)d_out;

    cudaFuncSetAttribute(lstm_persistent_kernel,
                         cudaFuncAttributeMaxDynamicSharedMemorySize, SMEM_TOTAL);

    dim3 ggrid(G4 / BN, (SEQT * BATCH) / BM, 2);   // (32, 256, 2)
    gemm_ih_kernel<<<ggrid, 256>>>(x, h0, w_ih_f, w_ih_r,
                                   b_ih_f, b_hh_f, b_ih_r, b_hh_r);

    lstm_persistent_kernel<<<2 * NBLK_PER_DIR, 256, SMEM_TOTAL>>>(
        w_hh_f, w_hh_r, c0, out);
}

// round 11
// speedup vs baseline: 1.2121x; 1.0065x over previous
#include <cuda_runtime.h>
#include <math.h>

#define BATCH 32
#define SEQT  512
#define HID   512
#define G4    2048   // 4*HID

// out layout (fp32): out[B][T][2H] @0, h_n[2][B][H] @16777216, c_n @16809984
#define OUT_HN 16777216
#define OUT_CN 16809984

// ---------------------------------------------------------------------------
// Device globals (allocation-free scratch), 256B-aligned for vector access.
// ---------------------------------------------------------------------------
// gx permuted per consumer block: [dir][blk(64)][t(512)][cl(32)][b(32)]
__device__ __align__(256) float g_gx[2][64][SEQT][32][32];
__device__ __align__(256) float g_hB[2][2][BATCH][HID];   // [parity][dir][batch][unit]
__device__ __align__(256) int   g_arrive[2];              // per-dir step counters

// ---------------------------------------------------------------------------
// Packed fp32x2 FMA (Blackwell FFMA2; only reachable via PTX)
// ---------------------------------------------------------------------------
__device__ __forceinline__ float2 f2fma(float2 a, float2 b, float2 c) {
    unsigned long long ra = *reinterpret_cast<unsigned long long*>(&a);
    unsigned long long rb = *reinterpret_cast<unsigned long long*>(&b);
    unsigned long long rc = *reinterpret_cast<unsigned long long*>(&c);
    unsigned long long rd;
    asm("fma.rn.f32x2 %0, %1, %2, %3;" : "=l"(rd) : "l"(ra), "l"(rb), "l"(rc));
    return *reinterpret_cast<float2*>(&rd);
}
__device__ __forceinline__ float2 f2(float x, float y) { return make_float2(x, y); }

__device__ __forceinline__ float sigf(float x) { return 1.0f / (1.0f + __expf(-x)); }
__device__ __forceinline__ float tanhx(float x) { return 2.0f / (1.0f + __expf(-2.0f * x)) - 1.0f; }

// ---------------------------------------------------------------------------
// Phase 1: gx = x @ W_ih^T + biases (written permuted). Init of h/counters is
// embedded. BM=BN=64, BK=16, 256 thr, 4x4 microtile, dup'd-A f32x2 (unchanged).
// ---------------------------------------------------------------------------
#define BM 64
#define BN 64
#define BK 16

__global__ __launch_bounds__(256) void gemm_ih_kernel(
        const float* __restrict__ x,
        const float* __restrict__ h0,
        const float* __restrict__ w_f, const float* __restrict__ w_r,
        const float* __restrict__ bi_f, const float* __restrict__ bh_f,
        const float* __restrict__ bi_r, const float* __restrict__ bh_r) {
    const int tid = threadIdx.x;

    // ---- embedded init (h0 -> g_hB[0] (identical linear layout), counters) ----
    {
        const int gid = (blockIdx.z * gridDim.y + blockIdx.y) * gridDim.x + blockIdx.x;
        if (gid < 128) {
            const int idx = gid * 256 + tid;     // 0..32767
            (&g_hB[0][0][0][0])[idx] = h0[idx];  // [dir][b][j] matches h0 layout
        }
        if (gid == 0 && tid < 2) g_arrive[tid] = 0;
    }

    const int dir = blockIdx.z;
    const float* __restrict__ w  = dir ? w_r  : w_f;
    const float* __restrict__ bi = dir ? bi_r : bi_f;
    const float* __restrict__ bh = dir ? bh_r : bh_f;

    const int rm0 = blockIdx.y * BM;   // rows over T*B (row = t*32+b)
    const int cn0 = blockIdx.x * BN;   // cols over 4H

    __shared__ __align__(16) float2 Asd[BK][BM + 2];   // A rows, duplicated lanes
    __shared__ __align__(16) float  Ws[BK][BN + 4];

    const int tr = tid / 16;           // 0..15 row group
    const int tc = tid % 16;           // 0..15 col group

    const int l_row = tid >> 2;        // 0..63
    const int l_k4  = (tid & 3) << 2;  // 0,4,8,12

    const int r  = rm0 + l_row;
    int       tt = r >> 5;
    const int bb = r & 31;
    if (dir) tt = (SEQT - 1) - tt;
    const float* a_ptr = x + ((size_t)bb * SEQT + tt) * HID;
    const float* w_ptr = w + (size_t)(cn0 + l_row) * HID;

    float2 acc[4][2];
#pragma unroll
    for (int i = 0; i < 4; i++) { acc[i][0] = f2(0.f, 0.f); acc[i][1] = f2(0.f, 0.f); }

    for (int k0 = 0; k0 < HID; k0 += BK) {
        float4 av = *(const float4*)(a_ptr + k0 + l_k4);
        float4 wv = *(const float4*)(w_ptr + k0 + l_k4);
        __syncthreads();
        Asd[l_k4 + 0][l_row] = f2(av.x, av.x);
        Asd[l_k4 + 1][l_row] = f2(av.y, av.y);
        Asd[l_k4 + 2][l_row] = f2(av.z, av.z);
        Asd[l_k4 + 3][l_row] = f2(av.w, av.w);
        Ws[l_k4 + 0][l_row] = wv.x;
        Ws[l_k4 + 1][l_row] = wv.y;
        Ws[l_k4 + 2][l_row] = wv.z;
        Ws[l_k4 + 3][l_row] = wv.w;
        __syncthreads();
#pragma unroll
        for (int kk = 0; kk < BK; kk++) {
            float4 ad0 = *(const float4*)&Asd[kk][tr * 4];
            float4 ad1 = *(const float4*)&Asd[kk][tr * 4 + 2];
            float4 w4  = *(const float4*)&Ws[kk][tc * 4];
            float2 w01 = f2(w4.x, w4.y);
            float2 w23 = f2(w4.z, w4.w);
            float2 a0 = f2(ad0.x, ad0.y);
            float2 a1 = f2(ad0.z, ad0.w);
            float2 a2 = f2(ad1.x, ad1.y);
            float2 a3 = f2(ad1.z, ad1.w);
            acc[0][0] = f2fma(a0, w01, acc[0][0]); acc[0][1] = f2fma(a0, w23, acc[0][1]);
            acc[1][0] = f2fma(a1, w01, acc[1][0]); acc[1][1] = f2fma(a1, w23, acc[1][1]);
            acc[2][0] = f2fma(a2, w01, acc[2][0]); acc[2][1] = f2fma(a2, w23, acc[2][1]);
            acc[3][0] = f2fma(a3, w01, acc[3][0]); acc[3][1] = f2fma(a3, w23, acc[3][1]);
        }
    }

    // epilogue: write permuted gx. col c -> (blk=(c&511)>>3, cl=(c>>9)*8+(c&7))
    const int cc = cn0 + tc * 4;
    float bsum[4], res[4];
#pragma unroll
    for (int j = 0; j < 4; j++) bsum[j] = bi[cc + j] + bh[cc + j];
#pragma unroll
    for (int i = 0; i < 4; i++) {
        const int rr = rm0 + tr * 4 + i;
        const int t = rr >> 5;
        const int b = rr & 31;
        res[0] = acc[i][0].x + bsum[0];
        res[1] = acc[i][0].y + bsum[1];
        res[2] = acc[i][1].x + bsum[2];
        res[3] = acc[i][1].y + bsum[3];
#pragma unroll
        for (int j = 0; j < 4; j++) {
            const int c = cc + j;
            const int blk = (c & 511) >> 3;
            const int cl = (c >> 9) * 8 + (c & 7);
            g_gx[dir][blk][t][cl][b] = res[j];
        }
    }
}

// ---------------------------------------------------------------------------
// Phase 2: persistent recurrence. 128 blocks (64/dir), 256 threads.
// W-in-registers GEMM (R10) + software-pipelined batch loop (unroll 4) so the
// LDS->FFMA2->butterfly latency chains of 4 independent batches overlap.
// ---------------------------------------------------------------------------
#define NBLK_PER_DIR 64
#define JB 8
#define PST 33                     // P row stride (floats); scalar access only

#define SM_HS 0                    // float Hs[32][512] = 65536 B
#define SM_P  65536                // float P[32][33]   =  4224 B
#define SM_HO 69760                // float HO[32][8]   =  1024 B
#define SMEM_TOTAL (69760 + 1024)

__global__ __launch_bounds__(256, 1)
void lstm_persistent_kernel(const float* __restrict__ w_hh_f,
                            const float* __restrict__ w_hh_r,
                            const float* __restrict__ c0,
                            float* __restrict__ out) {
    extern __shared__ __align__(16) char smem_raw[];
    float* Hs = (float*)(smem_raw + SM_HS);    // [b][k], stride 512
    float* P  = (float*)(smem_raw + SM_P);     // [c_local][b], stride PST
    float* HO = (float*)(smem_raw + SM_HO);    // [b][8]

    const int tid = threadIdx.x;
    const int dir = blockIdx.x >> 6;
    const int blk = blockIdx.x & 63;
    const int j0  = blk * JB;
    const float* __restrict__ w = dir ? w_hh_r : w_hh_f;
    int* arrive = &g_arrive[dir];

    const int wid  = tid >> 5;                 // 0..7
    const int lane = tid & 31;

    // ---- GEMM warp coords: hb = batch half, cq = gate; lane = k mod 32 ----
    const int hb = wid >> 2;                   // 0/1
    const int cq = wid & 3;                    // gate 0..3

    // ---- W registers: wreg[c8][jp] = (W[c][64jp+lane], W[c][64jp+32+lane]) ----
    float2 wreg[8][8];
#pragma unroll
    for (int c8 = 0; c8 < 8; c8++) {
        const float* wr = w + (size_t)(cq * HID + j0 + c8) * HID;
#pragma unroll
        for (int jp = 0; jp < 8; jp++)
            wreg[c8][jp] = f2(wr[jp * 64 + lane], wr[jp * 64 + 32 + lane]);
    }

    // reduction lane constants: final col owned = cmap, replicated over lane&3
    const bool hi16 = (lane & 16) != 0;
    const bool hi8  = (lane & 8)  != 0;
    const bool hi4  = (lane & 4)  != 0;
    const int  cmap = ((lane >> 4) & 1) * 4 + ((lane >> 3) & 1) * 2 + ((lane >> 2) & 1);
    float* pdst = &P[(cq * 8 + cmap) * PST + hb * 16];

    // ---- pointwise ownership: thread -> (u = wid, b = lane) ----
    const int pu = wid;
    const int pb = lane;
    float creg = c0[((size_t)dir * BATCH + pb) * HID + j0 + pu];

    const float4* hB0 = (const float4*)&g_hB[0][dir][0][0];
    const float4* hB1 = (const float4*)&g_hB[1][dir][0][0];
    float4* Hs4 = (float4*)Hs;
    const float* gxbase = &g_gx[dir][blk][0][0][0];

    __syncthreads();

    for (int t = 0; t < SEQT; t++) {
        // prefetch gx (pointwise mapping; coalesced; in flight during the wait)
        const float* gxp = gxbase + (size_t)t * 1024;
        float gxr0 = gxp[(pu)      * 32 + pb];
        float gxr1 = gxp[(8 + pu)  * 32 + pb];
        float gxr2 = gxp[(16 + pu) * 32 + pb];
        float gxr3 = gxp[(24 + pu) * 32 + pb];

        // wait for all same-dir blocks to finish step t-1
        if (t > 0 && tid == 0) {
            const int target = NBLK_PER_DIR * t;
            int v;
            do {
                asm volatile("ld.acquire.gpu.s32 %0, [%1];" : "=r"(v) : "l"(arrive));
            } while (v < target);
        }
        __syncthreads();

        // stage h (64KB) into Hs[b][k] — straight linear coalesced copy
        const float4* src = (t & 1) ? hB1 : hB0;
#pragma unroll
        for (int it = 0; it < 16; it++) Hs4[it * 256 + tid] = src[it * 256 + tid];
        __syncthreads();

        // GEMM: per batch: 16 LDS + 64 FFMA2 + butterfly reduce + 1 STS.
        // unroll 4: overlap the latency chains of 4 independent batches.
        const float* hbase = Hs + (hb * 16) * 512 + lane;
#pragma unroll 4
        for (int bi = 0; bi < 16; bi++) {
            const float* hp = hbase + bi * 512;
            float2 a0 = f2(0.f, 0.f), a1 = f2(0.f, 0.f), a2 = f2(0.f, 0.f), a3 = f2(0.f, 0.f);
            float2 a4 = f2(0.f, 0.f), a5 = f2(0.f, 0.f), a6 = f2(0.f, 0.f), a7 = f2(0.f, 0.f);
#pragma unroll
            for (int jp = 0; jp < 8; jp++) {
                float2 hv = f2(hp[jp * 64], hp[jp * 64 + 32]);
                a0 = f2fma(hv, wreg[0][jp], a0);
                a1 = f2fma(hv, wreg[1][jp], a1);
                a2 = f2fma(hv, wreg[2][jp], a2);
                a3 = f2fma(hv, wreg[3][jp], a3);
                a4 = f2fma(hv, wreg[4][jp], a4);
                a5 = f2fma(hv, wreg[5][jp], a5);
                a6 = f2fma(hv, wreg[6][jp], a6);
                a7 = f2fma(hv, wreg[7][jp], a7);
            }
            float v0 = a0.x + a0.y, v1 = a1.x + a1.y, v2 = a2.x + a2.y, v3 = a3.x + a3.y;
            float v4 = a4.x + a4.y, v5 = a5.x + a5.y, v6 = a6.x + a6.y, v7 = a7.x + a7.y;

            // value-halving butterfly over lanes (k-residues)
            float k0 = hi16 ? v4 : v0,  s0 = hi16 ? v0 : v4;
            float k1 = hi16 ? v5 : v1,  s1 = hi16 ? v1 : v5;
            float k2 = hi16 ? v6 : v2,  s2 = hi16 ? v2 : v6;
            float k3 = hi16 ? v7 : v3,  s3 = hi16 ? v3 : v7;
            k0 += __shfl_xor_sync(0xffffffffu, s0, 16);
            k1 += __shfl_xor_sync(0xffffffffu, s1, 16);
            k2 += __shfl_xor_sync(0xffffffffu, s2, 16);
            k3 += __shfl_xor_sync(0xffffffffu, s3, 16);
            float m0 = hi8 ? k2 : k0,  t0 = hi8 ? k0 : k2;
            float m1 = hi8 ? k3 : k1,  t1 = hi8 ? k1 : k3;
            m0 += __shfl_xor_sync(0xffffffffu, t0, 8);
            m1 += __shfl_xor_sync(0xffffffffu, t1, 8);
            float m = hi4 ? m1 : m0,  u = hi4 ? m0 : m1;
            m += __shfl_xor_sync(0xffffffffu, u, 4);
            m += __shfl_xor_sync(0xffffffffu, m, 2);
            m += __shfl_xor_sync(0xffffffffu, m, 1);
            if ((lane & 3) == 0) pdst[bi] = m;
        }
        __syncthreads();

        // pointwise: 1 item/thread
        {
            const float pi = P[(pu)      * PST + pb] + gxr0;
            const float pf = P[(8 + pu)  * PST + pb] + gxr1;
            const float pg = P[(16 + pu) * PST + pb] + gxr2;
            const float po = P[(24 + pu) * PST + pb] + gxr3;
            const float iv = sigf(pi);
            const float fv = sigf(pf);
            const float gv = tanhx(pg);
            const float ov = sigf(po);
            creg = fv * creg + iv * gv;
            const float hnew = ov * tanhx(creg);
            HO[pb * 8 + pu] = hnew;
            if (t == SEQT - 1) {
                out[OUT_HN + ((size_t)dir * BATCH + pb) * HID + j0 + pu] = hnew;
                out[OUT_CN + ((size_t)dir * BATCH + pb) * HID + j0 + pu] = creg;
            }
        }
        __syncthreads();   // HO visible

        // 128 threads: write next-h (coalesced) + out from HO bounce
        if (tid < 128) {
            const int ob = tid >> 2;
            const int ou = (tid & 3) * 2;
            float2 v = *(const float2*)&HO[ob * 8 + ou];
            float* hdst = (t & 1) ? (float*)&g_hB[0][dir][0][0]
                                  : (float*)&g_hB[1][dir][0][0];
            *(float2*)&hdst[ob * HID + j0 + ou] = v;
            const int tout = dir ? (SEQT - 1 - t) : t;
            *(float2*)&out[((size_t)ob * SEQT + tout) * (2 * HID) + dir * HID + j0 + ou] = v;
        }
        __syncthreads();   // h stores issued block-wide before the release

        // signal completion of step t
        if (tid == 0) {
            int dummy;
            asm volatile("atom.release.gpu.add.s32 %0, [%1], 1;"
                         : "=r"(dummy) : "l"(arrive));
        }
    }
}

// ---------------------------------------------------------------------------
// Launch
// ---------------------------------------------------------------------------
extern "C" void kernel_launch(void* const* d_in, const int* in_sizes, int n_in,
                              void* d_out, int out_size) {
    const float* x      = (const float*)d_in[0];
    const float* h0     = (const float*)d_in[1];
    const float* c0     = (const float*)d_in[2];
    const float* w_ih_f = (const float*)d_in[3];
    const float* w_hh_f = (const float*)d_in[4];
    const float* b_ih_f = (const float*)d_in[5];
    const float* b_hh_f = (const float*)d_in[6];
    const float* w_ih_r = (const float*)d_in[7];
    const float* w_hh_r = (const float*)d_in[8];
    const float* b_ih_r = (const float*)d_in[9];
    const float* b_hh_r = (const float*)d_in[10];
    float* out = (float*)d_out;

    cudaFuncSetAttribute(lstm_persistent_kernel,
                         cudaFuncAttributeMaxDynamicSharedMemorySize, SMEM_TOTAL);

    dim3 ggrid(G4 / BN, (SEQT * BATCH) / BM, 2);   // (32, 256, 2)
    gemm_ih_kernel<<<ggrid, 256>>>(x, h0, w_ih_f, w_ih_r,
                                   b_ih_f, b_hh_f, b_ih_r, b_hh_r);

    lstm_persistent_kernel<<<2 * NBLK_PER_DIR, 256, SMEM_TOTAL>>>(
        w_hh_f, w_hh_r, c0, out);
}

// round 12
// speedup vs baseline: 1.2122x; 1.0001x over previous
#include <cuda_runtime.h>
#include <math.h>

#define BATCH 32
#define SEQT  512
#define HID   512
#define G4    2048   // 4*HID

// out layout (fp32): out[B][T][2H] @0, h_n[2][B][H] @16777216, c_n @16809984
#define OUT_HN 16777216
#define OUT_CN 16809984

// ---------------------------------------------------------------------------
// Device globals (allocation-free scratch), 256B-aligned for vector access.
// ---------------------------------------------------------------------------
// gx permuted per consumer block: [dir][blk(64)][t(512)][cl(32)][b(32)]
__device__ __align__(256) float g_gx[2][64][SEQT][32][32];
__device__ __align__(256) float g_hB[2][2][BATCH][HID];   // [parity][dir][batch][unit]
// grouped step counters: 8 counters/dir, one 128B line each; blocks blk%8 -> cnt[blk&7]
__device__ __align__(256) int   g_cnt[2][8][32];

// ---------------------------------------------------------------------------
// Packed fp32x2 FMA (Blackwell FFMA2; only reachable via PTX)
// ---------------------------------------------------------------------------
__device__ __forceinline__ float2 f2fma(float2 a, float2 b, float2 c) {
    unsigned long long ra = *reinterpret_cast<unsigned long long*>(&a);
    unsigned long long rb = *reinterpret_cast<unsigned long long*>(&b);
    unsigned long long rc = *reinterpret_cast<unsigned long long*>(&c);
    unsigned long long rd;
    asm("fma.rn.f32x2 %0, %1, %2, %3;" : "=l"(rd) : "l"(ra), "l"(rb), "l"(rc));
    return *reinterpret_cast<float2*>(&rd);
}
__device__ __forceinline__ float2 f2(float x, float y) { return make_float2(x, y); }

__device__ __forceinline__ float sigf(float x) { return 1.0f / (1.0f + __expf(-x)); }
__device__ __forceinline__ float tanhx(float x) { return 2.0f / (1.0f + __expf(-2.0f * x)) - 1.0f; }

// ---------------------------------------------------------------------------
// Phase 1: gx = x @ W_ih^T + biases (written permuted). Init of h/counters is
// embedded. BM=BN=64, BK=16, 256 thr, 4x4 microtile, dup'd-A f32x2 (unchanged).
// ---------------------------------------------------------------------------
#define BM 64
#define BN 64
#define BK 16

__global__ __launch_bounds__(256) void gemm_ih_kernel(
        const float* __restrict__ x,
        const float* __restrict__ h0,
        const float* __restrict__ w_f, const float* __restrict__ w_r,
        const float* __restrict__ bi_f, const float* __restrict__ bh_f,
        const float* __restrict__ bi_r, const float* __restrict__ bh_r) {
    const int tid = threadIdx.x;

    // ---- embedded init (h0 -> g_hB[0] (identical linear layout), counters) ----
    {
        const int gid = (blockIdx.z * gridDim.y + blockIdx.y) * gridDim.x + blockIdx.x;
        if (gid < 128) {
            const int idx = gid * 256 + tid;     // 0..32767
            (&g_hB[0][0][0][0])[idx] = h0[idx];  // [dir][b][j] matches h0 layout
        }
        if (gid == 0 && tid < 16) g_cnt[tid >> 3][tid & 7][0] = 0;
    }

    const int dir = blockIdx.z;
    const float* __restrict__ w  = dir ? w_r  : w_f;
    const float* __restrict__ bi = dir ? bi_r : bi_f;
    const float* __restrict__ bh = dir ? bh_r : bh_f;

    const int rm0 = blockIdx.y * BM;   // rows over T*B (row = t*32+b)
    const int cn0 = blockIdx.x * BN;   // cols over 4H

    __shared__ __align__(16) float2 Asd[BK][BM + 2];   // A rows, duplicated lanes
    __shared__ __align__(16) float  Ws[BK][BN + 4];

    const int tr = tid / 16;           // 0..15 row group
    const int tc = tid % 16;           // 0..15 col group

    const int l_row = tid >> 2;        // 0..63
    const int l_k4  = (tid & 3) << 2;  // 0,4,8,12

    const int r  = rm0 + l_row;
    int       tt = r >> 5;
    const int bb = r & 31;
    if (dir) tt = (SEQT - 1) - tt;
    const float* a_ptr = x + ((size_t)bb * SEQT + tt) * HID;
    const float* w_ptr = w + (size_t)(cn0 + l_row) * HID;

    float2 acc[4][2];
#pragma unroll
    for (int i = 0; i < 4; i++) { acc[i][0] = f2(0.f, 0.f); acc[i][1] = f2(0.f, 0.f); }

    for (int k0 = 0; k0 < HID; k0 += BK) {
        float4 av = *(const float4*)(a_ptr + k0 + l_k4);
        float4 wv = *(const float4*)(w_ptr + k0 + l_k4);
        __syncthreads();
        Asd[l_k4 + 0][l_row] = f2(av.x, av.x);
        Asd[l_k4 + 1][l_row] = f2(av.y, av.y);
        Asd[l_k4 + 2][l_row] = f2(av.z, av.z);
        Asd[l_k4 + 3][l_row] = f2(av.w, av.w);
        Ws[l_k4 + 0][l_row] = wv.x;
        Ws[l_k4 + 1][l_row] = wv.y;
        Ws[l_k4 + 2][l_row] = wv.z;
        Ws[l_k4 + 3][l_row] = wv.w;
        __syncthreads();
#pragma unroll
        for (int kk = 0; kk < BK; kk++) {
            float4 ad0 = *(const float4*)&Asd[kk][tr * 4];
            float4 ad1 = *(const float4*)&Asd[kk][tr * 4 + 2];
            float4 w4  = *(const float4*)&Ws[kk][tc * 4];
            float2 w01 = f2(w4.x, w4.y);
            float2 w23 = f2(w4.z, w4.w);
            float2 a0 = f2(ad0.x, ad0.y);
            float2 a1 = f2(ad0.z, ad0.w);
            float2 a2 = f2(ad1.x, ad1.y);
            float2 a3 = f2(ad1.z, ad1.w);
            acc[0][0] = f2fma(a0, w01, acc[0][0]); acc[0][1] = f2fma(a0, w23, acc[0][1]);
            acc[1][0] = f2fma(a1, w01, acc[1][0]); acc[1][1] = f2fma(a1, w23, acc[1][1]);
            acc[2][0] = f2fma(a2, w01, acc[2][0]); acc[2][1] = f2fma(a2, w23, acc[2][1]);
            acc[3][0] = f2fma(a3, w01, acc[3][0]); acc[3][1] = f2fma(a3, w23, acc[3][1]);
        }
    }

    // epilogue: write permuted gx. col c -> (blk=(c&511)>>3, cl=(c>>9)*8+(c&7))
    const int cc = cn0 + tc * 4;
    float bsum[4], res[4];
#pragma unroll
    for (int j = 0; j < 4; j++) bsum[j] = bi[cc + j] + bh[cc + j];
#pragma unroll
    for (int i = 0; i < 4; i++) {
        const int rr = rm0 + tr * 4 + i;
        const int t = rr >> 5;
        const int b = rr & 31;
        res[0] = acc[i][0].x + bsum[0];
        res[1] = acc[i][0].y + bsum[1];
        res[2] = acc[i][1].x + bsum[2];
        res[3] = acc[i][1].y + bsum[3];
#pragma unroll
        for (int j = 0; j < 4; j++) {
            const int c = cc + j;
            const int blk = (c & 511) >> 3;
            const int cl = (c >> 9) * 8 + (c & 7);
            g_gx[dir][blk][t][cl][b] = res[j];
        }
    }
}

// ---------------------------------------------------------------------------
// Phase 2: persistent recurrence. 128 blocks (64/dir), 256 threads.
// W-in-registers GEMM (R10/R11). Sync: 8 grouped counters per dir — 8 blocks
// per counter (red.release, ~220cyc chain), 8 lanes poll 8 distinct lines.
// ---------------------------------------------------------------------------
#define NBLK_PER_DIR 64
#define JB 8
#define PST 33                     // P row stride (floats); scalar access only

#define SM_HS 0                    // float Hs[32][512] = 65536 B
#define SM_P  65536                // float P[32][33]   =  4224 B
#define SM_HO 69760                // float HO[32][8]   =  1024 B
#define SMEM_TOTAL (69760 + 1024)

__global__ __launch_bounds__(256, 1)
void lstm_persistent_kernel(const float* __restrict__ w_hh_f,
                            const float* __restrict__ w_hh_r,
                            const float* __restrict__ c0,
                            float* __restrict__ out) {
    extern __shared__ __align__(16) char smem_raw[];
    float* Hs = (float*)(smem_raw + SM_HS);    // [b][k], stride 512
    float* P  = (float*)(smem_raw + SM_P);     // [c_local][b], stride PST
    float* HO = (float*)(smem_raw + SM_HO);    // [b][8]

    const int tid = threadIdx.x;
    const int dir = blockIdx.x >> 6;
    const int blk = blockIdx.x & 63;
    const int j0  = blk * JB;
    const float* __restrict__ w = dir ? w_hh_r : w_hh_f;

    const int wid  = tid >> 5;                 // 0..7
    const int lane = tid & 31;

    // ---- GEMM warp coords: hb = batch half, cq = gate; lane = k mod 32 ----
    const int hb = wid >> 2;                   // 0/1
    const int cq = wid & 3;                    // gate 0..3

    // ---- W registers: wreg[c8][jp] = (W[c][64jp+lane], W[c][64jp+32+lane]) ----
    float2 wreg[8][8];
#pragma unroll
    for (int c8 = 0; c8 < 8; c8++) {
        const float* wr = w + (size_t)(cq * HID + j0 + c8) * HID;
#pragma unroll
        for (int jp = 0; jp < 8; jp++)
            wreg[c8][jp] = f2(wr[jp * 64 + lane], wr[jp * 64 + 32 + lane]);
    }

    // reduction lane constants: final col owned = cmap, replicated over lane&3
    const bool hi16 = (lane & 16) != 0;
    const bool hi8  = (lane & 8)  != 0;
    const bool hi4  = (lane & 4)  != 0;
    const int  cmap = ((lane >> 4) & 1) * 4 + ((lane >> 3) & 1) * 2 + ((lane >> 2) & 1);
    float* pdst = &P[(cq * 8 + cmap) * PST + hb * 16];

    // ---- pointwise ownership: thread -> (u = wid, b = lane) ----
    const int pu = wid;
    const int pb = lane;
    float creg = c0[((size_t)dir * BATCH + pb) * HID + j0 + pu];

    const float4* hB0 = (const float4*)&g_hB[0][dir][0][0];
    const float4* hB1 = (const float4*)&g_hB[1][dir][0][0];
    float4* Hs4 = (float4*)Hs;
    const float* gxbase = &g_gx[dir][blk][0][0][0];
    int* mycnt   = &g_cnt[dir][blk & 7][0];
    int* pollcnt = &g_cnt[dir][tid & 7][0];    // used by lanes 0-7 only

    __syncthreads();

    for (int t = 0; t < SEQT; t++) {
        // prefetch gx (pointwise mapping; coalesced; in flight during the wait)
        const float* gxp = gxbase + (size_t)t * 1024;
        float gxr0 = gxp[(pu)      * 32 + pb];
        float gxr1 = gxp[(8 + pu)  * 32 + pb];
        float gxr2 = gxp[(16 + pu) * 32 + pb];
        float gxr3 = gxp[(24 + pu) * 32 + pb];

        // wait: lanes 0-7 each poll one grouped counter (8 blocks per counter)
        if (t > 0 && tid < 8) {
            const int target = 8 * t;
            int v;
            do {
                asm volatile("ld.acquire.gpu.s32 %0, [%1];" : "=r"(v) : "l"(pollcnt));
            } while (v < target);
        }
        __syncthreads();

        // stage h (64KB) into Hs[b][k] — straight linear coalesced copy
        const float4* src = (t & 1) ? hB1 : hB0;
#pragma unroll
        for (int it = 0; it < 16; it++) Hs4[it * 256 + tid] = src[it * 256 + tid];
        __syncthreads();

        // GEMM: per batch: 16 LDS + 64 FFMA2 + butterfly reduce + 1 STS.
        const float* hbase = Hs + (hb * 16) * 512 + lane;
#pragma unroll 4
        for (int bi = 0; bi < 16; bi++) {
            const float* hp = hbase + bi * 512;
            float2 a0 = f2(0.f, 0.f), a1 = f2(0.f, 0.f), a2 = f2(0.f, 0.f), a3 = f2(0.f, 0.f);
            float2 a4 = f2(0.f, 0.f), a5 = f2(0.f, 0.f), a6 = f2(0.f, 0.f), a7 = f2(0.f, 0.f);
#pragma unroll
            for (int jp = 0; jp < 8; jp++) {
                float2 hv = f2(hp[jp * 64], hp[jp * 64 + 32]);
                a0 = f2fma(hv, wreg[0][jp], a0);
                a1 = f2fma(hv, wreg[1][jp], a1);
                a2 = f2fma(hv, wreg[2][jp], a2);
                a3 = f2fma(hv, wreg[3][jp], a3);
                a4 = f2fma(hv, wreg[4][jp], a4);
                a5 = f2fma(hv, wreg[5][jp], a5);
                a6 = f2fma(hv, wreg[6][jp], a6);
                a7 = f2fma(hv, wreg[7][jp], a7);
            }
            float v0 = a0.x + a0.y, v1 = a1.x + a1.y, v2 = a2.x + a2.y, v3 = a3.x + a3.y;
            float v4 = a4.x + a4.y, v5 = a5.x + a5.y, v6 = a6.x + a6.y, v7 = a7.x + a7.y;

            // value-halving butterfly over lanes (k-residues)
            float k0 = hi16 ? v4 : v0,  s0 = hi16 ? v0 : v4;
            float k1 = hi16 ? v5 : v1,  s1 = hi16 ? v1 : v5;
            float k2 = hi16 ? v6 : v2,  s2 = hi16 ? v2 : v6;
            float k3 = hi16 ? v7 : v3,  s3 = hi16 ? v3 : v7;
            k0 += __shfl_xor_sync(0xffffffffu, s0, 16);
            k1 += __shfl_xor_sync(0xffffffffu, s1, 16);
            k2 += __shfl_xor_sync(0xffffffffu, s2, 16);
            k3 += __shfl_xor_sync(0xffffffffu, s3, 16);
            float m0 = hi8 ? k2 : k0,  t0 = hi8 ? k0 : k2;
            float m1 = hi8 ? k3 : k1,  t1 = hi8 ? k1 : k3;
            m0 += __shfl_xor_sync(0xffffffffu, t0, 8);
            m1 += __shfl_xor_sync(0xffffffffu, t1, 8);
            float m = hi4 ? m1 : m0,  u = hi4 ? m0 : m1;
            m += __shfl_xor_sync(0xffffffffu, u, 4);
            m += __shfl_xor_sync(0xffffffffu, m, 2);
            m += __shfl_xor_sync(0xffffffffu, m, 1);
            if ((lane & 3) == 0) pdst[bi] = m;
        }
        __syncthreads();

        // pointwise: 1 item/thread
        {
            const float pi = P[(pu)      * PST + pb] + gxr0;
            const float pf = P[(8 + pu)  * PST + pb] + gxr1;
            const float pg = P[(16 + pu) * PST + pb] + gxr2;
            const float po = P[(24 + pu) * PST + pb] + gxr3;
            const float iv = sigf(pi);
            const float fv = sigf(pf);
            const float gv = tanhx(pg);
            const float ov = sigf(po);
            creg = fv * creg + iv * gv;
            const float hnew = ov * tanhx(creg);
            HO[pb * 8 + pu] = hnew;
            if (t == SEQT - 1) {
                out[OUT_HN + ((size_t)dir * BATCH + pb) * HID + j0 + pu] = hnew;
                out[OUT_CN + ((size_t)dir * BATCH + pb) * HID + j0 + pu] = creg;
            }
        }
        __syncthreads();   // HO visible

        // 128 threads: write next-h (coalesced) from HO bounce — critical path
        if (tid < 128) {
            const int ob = tid >> 2;
            const int ou = (tid & 3) * 2;
            float2 v = *(const float2*)&HO[ob * 8 + ou];
            float* hdst = (t & 1) ? (float*)&g_hB[0][dir][0][0]
                                  : (float*)&g_hB[1][dir][0][0];
            *(float2*)&hdst[ob * HID + j0 + ou] = v;
        }
        __syncthreads();   // h stores issued block-wide before the release

        // signal completion of step t (grouped counter; no return value)
        if (tid == 0) {
            asm volatile("red.release.gpu.add.s32 [%0], %1;"
                         :: "l"(mycnt), "r"(1));
        }

        // out write — off the critical path (HO stable until next pointwise,
        // which is behind two barriers in the next iteration)
        if (tid < 128) {
            const int ob = tid >> 2;
            const int ou = (tid & 3) * 2;
            float2 v = *(const float2*)&HO[ob * 8 + ou];
            const int tout = dir ? (SEQT - 1 - t) : t;
            *(float2*)&out[((size_t)ob * SEQT + tout) * (2 * HID) + dir * HID + j0 + ou] = v;
        }
    }
}

// ---------------------------------------------------------------------------
// Launch
// ---------------------------------------------------------------------------
extern "C" void kernel_launch(void* const* d_in, const int* in_sizes, int n_in,
                              void* d_out, int out_size) {
    const float* x      = (const float*)d_in[0];
    const float* h0     = (const float*)d_in[1];
    const float* c0     = (const float*)d_in[2];
    const float* w_ih_f = (const float*)d_in[3];
    const float* w_hh_f = (const float*)d_in[4];
    const float* b_ih_f = (const float*)d_in[5];
    const float* b_hh_f = (const float*)d_in[6];
    const float* w_ih_r = (const float*)d_in[7];
    const float* w_hh_r = (const float*)d_in[8];
    const float* b_ih_r = (const float*)d_in[9];
    const float* b_hh_r = (const float*)d_in[10];
    float* out = (float*)d_out;

    cudaFuncSetAttribute(lstm_persistent_kernel,
                         cudaFuncAttributeMaxDynamicSharedMemorySize, SMEM_TOTAL);

    dim3 ggrid(G4 / BN, (SEQT * BATCH) / BM, 2);   // (32, 256, 2)
    gemm_ih_kernel<<<ggrid, 256>>>(x, h0, w_ih_f, w_ih_r,
                                   b_ih_f, b_hh_f, b_ih_r, b_hh_r);

    lstm_persistent_kernel<<<2 * NBLK_PER_DIR, 256, SMEM_TOTAL>>>(
        w_hh_f, w_hh_r, c0, out);
}